// round 1
// baseline (speedup 1.0000x reference)
#include <cuda_runtime.h>
#include <math.h>
#include <stdint.h>

// Problem constants (fixed shapes from reference)
static const int S_TOK = 8192;          // B*T
static const int D_DIM = 1024;
static const int F_DIM = 4096;
static const int E_NUM = 8;
static const int CAP   = 2560;          // int(1.25 * S*K / E)
static const int A_NUM = S_TOK * 2;     // S*K assignments

// ---------------- device scratch (static: no allocs allowed) ----------------
__device__ float g_probs[S_TOK * E_NUM];
__device__ int   g_eidx[A_NUM];
__device__ float g_gate[A_NUM];
__device__ int   g_pos[A_NUM];
__device__ int   g_counts[E_NUM];
__device__ int   g_cnt[E_NUM];          // min(counts, CAP)
__device__ float g_importance[E_NUM];
__device__ float g_buf[(size_t)E_NUM * CAP * D_DIM];   // dispatched tokens (rows >= cnt stay 0)
__device__ float g_h  [(size_t)E_NUM * CAP * F_DIM];   // gelu(fc1)
__device__ float g_eo [(size_t)E_NUM * CAP * D_DIM];   // fc2 + b2 + residual

// ---------------- routing: logits, softmax, top-2 ----------------
__global__ void routing_kernel(const float* __restrict__ x, const float* __restrict__ wg) {
    __shared__ float swg[E_NUM * D_DIM];   // 32 KB
    const int s = blockIdx.x;
    const int tid = threadIdx.x;           // 256 threads
    for (int i = tid; i < E_NUM * D_DIM; i += 256) swg[i] = wg[i];
    __syncthreads();

    const float* xr = x + (size_t)s * D_DIM;
    float p[E_NUM];
#pragma unroll
    for (int e = 0; e < E_NUM; e++) p[e] = 0.f;
    for (int d = tid; d < D_DIM; d += 256) {
        float xv = xr[d];
#pragma unroll
        for (int e = 0; e < E_NUM; e++) p[e] = fmaf(xv, swg[e * D_DIM + d], p[e]);
    }
    // warp reduce then cross-warp
#pragma unroll
    for (int e = 0; e < E_NUM; e++)
        for (int o = 16; o > 0; o >>= 1) p[e] += __shfl_down_sync(0xffffffffu, p[e], o);

    __shared__ float wsum[8][E_NUM];
    const int wid = tid >> 5, lane = tid & 31;
    if (lane == 0) {
#pragma unroll
        for (int e = 0; e < E_NUM; e++) wsum[wid][e] = p[e];
    }
    __syncthreads();
    if (tid == 0) {
        float l[E_NUM];
#pragma unroll
        for (int e = 0; e < E_NUM; e++) {
            float a = 0.f;
#pragma unroll
            for (int w = 0; w < 8; w++) a += wsum[w][e];
            l[e] = a;
        }
        float mx = l[0];
#pragma unroll
        for (int e = 1; e < E_NUM; e++) mx = fmaxf(mx, l[e]);
        float pr[E_NUM], se = 0.f;
#pragma unroll
        for (int e = 0; e < E_NUM; e++) { pr[e] = expf(l[e] - mx); se += pr[e]; }
        const float inv = 1.f / se;
#pragma unroll
        for (int e = 0; e < E_NUM; e++) { pr[e] *= inv; g_probs[s * E_NUM + e] = pr[e]; }
        // top-2 on logits (same order as probs; stable lowest-index tie-break)
        int b0 = 0;
#pragma unroll
        for (int e = 1; e < E_NUM; e++) if (l[e] > l[b0]) b0 = e;
        int b1 = -1;
#pragma unroll
        for (int e = 0; e < E_NUM; e++) {
            if (e == b0) continue;
            if (b1 < 0 || l[e] > l[b1]) b1 = e;
        }
        g_eidx[s * 2 + 0] = b0;  g_gate[s * 2 + 0] = pr[b0];
        g_eidx[s * 2 + 1] = b1;  g_gate[s * 2 + 1] = pr[b1];
    }
}

// ---------------- capacity scan: arrival-order position per expert ----------------
__global__ void scan_kernel() {
    __shared__ int hist[256][E_NUM];
    const int t = threadIdx.x;
    const int base = t * 64;                 // 256 * 64 = 16384 assignments
    int loc[E_NUM];
#pragma unroll
    for (int e = 0; e < E_NUM; e++) loc[e] = 0;
    for (int i = 0; i < 64; i++) loc[g_eidx[base + i]]++;
#pragma unroll
    for (int e = 0; e < E_NUM; e++) hist[t][e] = loc[e];
    __syncthreads();
    if (t < E_NUM) {
        int run = 0;
        for (int i = 0; i < 256; i++) { int v = hist[i][t]; hist[i][t] = run; run += v; }
        g_counts[t] = run;
        g_cnt[t] = run < CAP ? run : CAP;
    }
    __syncthreads();
    int off[E_NUM];
#pragma unroll
    for (int e = 0; e < E_NUM; e++) off[e] = hist[t][e];
    for (int i = 0; i < 64; i++) {
        int e = g_eidx[base + i];
        g_pos[base + i] = off[e]++;
    }
}

// ---------------- dispatch: tokens -> g_buf[e][pos][:] ----------------
__global__ void dispatch_kernel(const float* __restrict__ x) {
    const int a = blockIdx.x;
    const int p = g_pos[a];
    if (p >= CAP) return;
    const int e = g_eidx[a];
    const int t = a >> 1;
    const float4* src = (const float4*)(x + (size_t)t * D_DIM);
    float4* dst = (float4*)(g_buf + ((size_t)e * CAP + p) * D_DIM);
    dst[threadIdx.x] = src[threadIdx.x];   // 256 * float4 = 1024 floats
}

// ---------------- grouped GEMM: C[m,n] = sum_k A[m,k] * B[n,k] (+epilogue) ----------------
// MODE 0: A=g_buf, B=W1[e] (F x D), out=g_h, epilogue gelu(v + b1)
// MODE 1: A=g_h,   B=W2[e] (D x F), out=g_eo, epilogue v + b2 + g_buf residual
template<int KDIM, int NDIM, int MODE>
__global__ void __launch_bounds__(256, 2)
gemm_kernel(const float* __restrict__ Bw, const float* __restrict__ bias_g) {
    const int e = blockIdx.z;
    const int cnt = g_cnt[e];
    const int m0 = blockIdx.y * 128;
    if (m0 >= cnt) return;                 // skip fully-empty tiles
    const int n0 = blockIdx.x * 128;

    const float* A    = (MODE == 0 ? g_buf : g_h) + (size_t)e * CAP * KDIM;
    const float* B    = Bw + (size_t)e * NDIM * KDIM;
    const float* bias = bias_g + (size_t)e * NDIM;
    float* out        = (MODE == 0 ? g_h : g_eo) + (size_t)e * CAP * NDIM;

    __shared__ float As[8][128];
    __shared__ float Bs[8][128];

    const int tid = threadIdx.x;
    const int tx = tid & 15;
    const int ty = tid >> 4;
    const int lr = tid >> 1;               // tile row to load (0..127)
    const int lc = (tid & 1) * 4;          // k offset (0 or 4)

    const float* Aptr = A + (size_t)(m0 + lr) * KDIM + lc;
    const float* Bptr = B + (size_t)(n0 + lr) * KDIM + lc;

    float acc[8][8];
#pragma unroll
    for (int i = 0; i < 8; i++)
#pragma unroll
        for (int j = 0; j < 8; j++) acc[i][j] = 0.f;

    for (int kt = 0; kt < KDIM; kt += 8) {
        const float4 av = *(const float4*)(Aptr + kt);
        const float4 bv = *(const float4*)(Bptr + kt);
        __syncthreads();
        As[lc + 0][lr] = av.x; As[lc + 1][lr] = av.y; As[lc + 2][lr] = av.z; As[lc + 3][lr] = av.w;
        Bs[lc + 0][lr] = bv.x; Bs[lc + 1][lr] = bv.y; Bs[lc + 2][lr] = bv.z; Bs[lc + 3][lr] = bv.w;
        __syncthreads();
#pragma unroll
        for (int k = 0; k < 8; k++) {
            const float4 a0 = *(const float4*)&As[k][ty * 8];
            const float4 a1 = *(const float4*)&As[k][ty * 8 + 4];
            const float4 b0 = *(const float4*)&Bs[k][tx * 8];
            const float4 b1 = *(const float4*)&Bs[k][tx * 8 + 4];
            const float aa[8] = {a0.x, a0.y, a0.z, a0.w, a1.x, a1.y, a1.z, a1.w};
            const float bb[8] = {b0.x, b0.y, b0.z, b0.w, b1.x, b1.y, b1.z, b1.w};
#pragma unroll
            for (int i = 0; i < 8; i++)
#pragma unroll
                for (int j = 0; j < 8; j++)
                    acc[i][j] = fmaf(aa[i], bb[j], acc[i][j]);
        }
    }

#pragma unroll
    for (int i = 0; i < 8; i++) {
        const int m = m0 + ty * 8 + i;
#pragma unroll
        for (int j = 0; j < 8; j++) {
            const int n = n0 + tx * 8 + j;
            float v = acc[i][j] + bias[n];
            if (MODE == 0) {
                v = 0.5f * v * (1.f + erff(v * 0.70710678118654752f));   // exact gelu
            } else {
                v += g_buf[((size_t)e * CAP + m) * D_DIM + n];           // residual (NDIM==D_DIM)
            }
            out[(size_t)m * NDIM + n] = v;
        }
    }
}

// ---------------- combine: y[t] = sum_k w_k * eo[e_k][pos_k] (no atomics) ----------------
__global__ void combine_kernel(float* __restrict__ y) {
    const int s = blockIdx.x;
    const int a0 = 2 * s, a1 = 2 * s + 1;
    const int p0 = g_pos[a0], p1 = g_pos[a1];
    const float w0 = (p0 < CAP) ? g_gate[a0] : 0.f;
    const float w1 = (p1 < CAP) ? g_gate[a1] : 0.f;
    const int q0 = p0 < CAP ? p0 : CAP - 1;
    const int q1 = p1 < CAP ? p1 : CAP - 1;
    const float4* r0 = (const float4*)(g_eo + ((size_t)g_eidx[a0] * CAP + q0) * D_DIM);
    const float4* r1 = (const float4*)(g_eo + ((size_t)g_eidx[a1] * CAP + q1) * D_DIM);
    float4* yo = (float4*)(y + (size_t)s * D_DIM);
    const int i = threadIdx.x;             // 256 * float4 = 1024
    const float4 v0 = r0[i];
    const float4 v1 = r1[i];
    float4 o;
    o.x = w0 * v0.x + w1 * v1.x;
    o.y = w0 * v0.y + w1 * v1.y;
    o.z = w0 * v0.z + w1 * v1.z;
    o.w = w0 * v0.w + w1 * v1.w;
    yo[i] = o;
}

// ---------------- aux loss (deterministic fixed-order reductions) ----------------
__global__ void importance_kernel() {
    __shared__ float sm[256];
    const int e = blockIdx.x;
    float a = 0.f;
    for (int s = threadIdx.x; s < S_TOK; s += 256) a += g_probs[s * E_NUM + e];
    sm[threadIdx.x] = a;
    __syncthreads();
    for (int o = 128; o > 0; o >>= 1) {
        if (threadIdx.x < o) sm[threadIdx.x] += sm[threadIdx.x + o];
        __syncthreads();
    }
    if (threadIdx.x == 0) g_importance[e] = sm[0];
}

__global__ void aux_kernel(float* __restrict__ out, int out_size) {
    if (threadIdx.x == 0) {
        float a = 0.f;
#pragma unroll
        for (int e = 0; e < E_NUM; e++)
            a += (g_importance[e] / (float)S_TOK) * ((float)g_counts[e] / (float)S_TOK);
        out[out_size - 1] = (float)E_NUM * a;
    }
}

// ---------------- launch ----------------
extern "C" void kernel_launch(void* const* d_in, const int* in_sizes, int n_in,
                              void* d_out, int out_size) {
    const float* x  = (const float*)d_in[0];
    const float* wg = (const float*)d_in[1];
    const float* W1 = (const float*)d_in[2];
    const float* b1 = (const float*)d_in[3];
    const float* W2 = (const float*)d_in[4];
    const float* b2 = (const float*)d_in[5];
    float* out = (float*)d_out;

    routing_kernel<<<S_TOK, 256>>>(x, wg);
    scan_kernel<<<1, 256>>>();
    dispatch_kernel<<<A_NUM, 256>>>(x);
    gemm_kernel<D_DIM, F_DIM, 0><<<dim3(F_DIM / 128, CAP / 128, E_NUM), 256>>>(W1, b1);
    gemm_kernel<F_DIM, D_DIM, 1><<<dim3(D_DIM / 128, CAP / 128, E_NUM), 256>>>(W2, b2);
    combine_kernel<<<S_TOK, 256>>>(out);
    importance_kernel<<<E_NUM, 256>>>();
    aux_kernel<<<1, 32>>>(out, out_size);
}

// round 11
// speedup vs baseline: 2.8821x; 2.8821x over previous
#include <cuda_runtime.h>
#include <cuda_bf16.h>
#include <math.h>
#include <stdint.h>

// ---------------- problem constants ----------------
#define S_TOK 8192
#define D_DIM 1024
#define F_DIM 4096
#define E_NUM 8
#define CAP   2560
#define A_NUM (S_TOK * 2)

// ---------------- device scratch ----------------
__device__ float g_probs[S_TOK * E_NUM];
__device__ int   g_eidx[A_NUM];
__device__ float g_gate[A_NUM];
__device__ int   g_pos[A_NUM];
__device__ int   g_counts[E_NUM];
__device__ int   g_cnt[E_NUM];
__device__ float g_importance[E_NUM];

__device__ __align__(1024) __nv_bfloat16 g_bufh[(size_t)E_NUM * CAP * D_DIM];
__device__ __align__(1024) __nv_bfloat16 g_bufl[(size_t)E_NUM * CAP * D_DIM];
__device__ __align__(1024) __nv_bfloat16 g_hh[(size_t)E_NUM * CAP * F_DIM];
__device__ __align__(1024) __nv_bfloat16 g_hl[(size_t)E_NUM * CAP * F_DIM];
__device__ __align__(1024) __nv_bfloat16 g_w1h[(size_t)E_NUM * F_DIM * D_DIM];
__device__ __align__(1024) __nv_bfloat16 g_w1l[(size_t)E_NUM * F_DIM * D_DIM];
__device__ __align__(1024) __nv_bfloat16 g_w2h[(size_t)E_NUM * D_DIM * F_DIM];
__device__ __align__(1024) __nv_bfloat16 g_w2l[(size_t)E_NUM * D_DIM * F_DIM];
__device__ __align__(1024) float g_eo[(size_t)E_NUM * CAP * D_DIM];

// ---------------- helpers ----------------
__device__ __forceinline__ uint32_t smem_u32(const void* p) {
    uint32_t a;
    asm("{ .reg .u64 t; cvta.to.shared.u64 t, %1; cvt.u32.u64 %0, t; }" : "=r"(a) : "l"(p));
    return a;
}
__device__ __forceinline__ float gelu_f(float v) {
    return 0.5f * v * (1.0f + erff(v * 0.70710678118654752f));
}

#define CP_ASYNC16(sa, ga) \
    asm volatile("cp.async.cg.shared.global [%0], [%1], 16;" :: "r"(sa), "l"(ga) : "memory")
#define CP_COMMIT() asm volatile("cp.async.commit_group;" ::: "memory")
#define CP_WAIT2()  asm volatile("cp.async.wait_group 2;" ::: "memory")

#define LDSM4(R, addr) \
    asm volatile("ldmatrix.sync.aligned.m8n8.x4.shared.b16 {%0,%1,%2,%3}, [%4];" \
        : "=r"((R)[0]), "=r"((R)[1]), "=r"((R)[2]), "=r"((R)[3]) : "r"(addr))

#define MMA_BF16(D, A, B) \
    asm volatile("mma.sync.aligned.m16n8k16.row.col.f32.bf16.bf16.f32 " \
        "{%0,%1,%2,%3}, {%4,%5,%6,%7}, {%8,%9}, {%0,%1,%2,%3};" \
        : "+f"((D)[0]), "+f"((D)[1]), "+f"((D)[2]), "+f"((D)[3]) \
        : "r"((A)[0]), "r"((A)[1]), "r"((A)[2]), "r"((A)[3]), "r"((B)[0]), "r"((B)[1]))

// ---------------- routing ----------------
__global__ void routing_kernel(const float* __restrict__ x, const float* __restrict__ wg) {
    __shared__ float swg[E_NUM * D_DIM];
    const int s = blockIdx.x;
    const int tid = threadIdx.x;
    for (int i = tid; i < E_NUM * D_DIM; i += 256) swg[i] = wg[i];
    __syncthreads();
    const float* xr = x + (size_t)s * D_DIM;
    float p[E_NUM];
#pragma unroll
    for (int e = 0; e < E_NUM; e++) p[e] = 0.f;
    for (int d = tid; d < D_DIM; d += 256) {
        float xv = xr[d];
#pragma unroll
        for (int e = 0; e < E_NUM; e++) p[e] = fmaf(xv, swg[e * D_DIM + d], p[e]);
    }
#pragma unroll
    for (int e = 0; e < E_NUM; e++)
        for (int o = 16; o > 0; o >>= 1) p[e] += __shfl_down_sync(0xffffffffu, p[e], o);
    __shared__ float wsum[8][E_NUM];
    const int wid = tid >> 5, lane = tid & 31;
    if (lane == 0) {
#pragma unroll
        for (int e = 0; e < E_NUM; e++) wsum[wid][e] = p[e];
    }
    __syncthreads();
    if (tid == 0) {
        float l[E_NUM];
#pragma unroll
        for (int e = 0; e < E_NUM; e++) {
            float a = 0.f;
#pragma unroll
            for (int w = 0; w < 8; w++) a += wsum[w][e];
            l[e] = a;
        }
        float mx = l[0];
#pragma unroll
        for (int e = 1; e < E_NUM; e++) mx = fmaxf(mx, l[e]);
        float pr[E_NUM], se = 0.f;
#pragma unroll
        for (int e = 0; e < E_NUM; e++) { pr[e] = expf(l[e] - mx); se += pr[e]; }
        const float inv = 1.f / se;
#pragma unroll
        for (int e = 0; e < E_NUM; e++) { pr[e] *= inv; g_probs[s * E_NUM + e] = pr[e]; }
        int b0 = 0;
#pragma unroll
        for (int e = 1; e < E_NUM; e++) if (l[e] > l[b0]) b0 = e;
        int b1 = -1;
#pragma unroll
        for (int e = 0; e < E_NUM; e++) {
            if (e == b0) continue;
            if (b1 < 0 || l[e] > l[b1]) b1 = e;
        }
        g_eidx[s * 2 + 0] = b0;  g_gate[s * 2 + 0] = pr[b0];
        g_eidx[s * 2 + 1] = b1;  g_gate[s * 2 + 1] = pr[b1];
    }
}

// ---------------- capacity scan ----------------
__global__ void scan_kernel() {
    __shared__ int hist[256][E_NUM];
    const int t = threadIdx.x;
    const int base = t * 64;
    int loc[E_NUM];
#pragma unroll
    for (int e = 0; e < E_NUM; e++) loc[e] = 0;
    for (int i = 0; i < 64; i++) loc[g_eidx[base + i]]++;
#pragma unroll
    for (int e = 0; e < E_NUM; e++) hist[t][e] = loc[e];
    __syncthreads();
    if (t < E_NUM) {
        int run = 0;
        for (int i = 0; i < 256; i++) { int v = hist[i][t]; hist[i][t] = run; run += v; }
        g_counts[t] = run;
        g_cnt[t] = run < CAP ? run : CAP;
    }
    __syncthreads();
    int off[E_NUM];
#pragma unroll
    for (int e = 0; e < E_NUM; e++) off[e] = hist[t][e];
    for (int i = 0; i < 64; i++) {
        int e = g_eidx[base + i];
        g_pos[base + i] = off[e]++;
    }
}

// ---------------- dispatch: tokens -> bf16 hi/lo buffers ----------------
__global__ void dispatch_kernel(const float* __restrict__ x) {
    const int a = blockIdx.x;
    const int p = g_pos[a];
    if (p >= CAP) return;
    const int e = g_eidx[a];
    const int t = a >> 1;
    const float4 v = ((const float4*)(x + (size_t)t * D_DIM))[threadIdx.x];
    const size_t base = ((size_t)e * CAP + p) * D_DIM + threadIdx.x * 4;
    float vv[4] = {v.x, v.y, v.z, v.w};
    __nv_bfloat16 h[4], l[4];
#pragma unroll
    for (int i = 0; i < 4; i++) {
        h[i] = __float2bfloat16(vv[i]);
        l[i] = __float2bfloat16(vv[i] - __bfloat162float(h[i]));
    }
    *(__nv_bfloat162*)(g_bufh + base)     = __halves2bfloat162(h[0], h[1]);
    *(__nv_bfloat162*)(g_bufh + base + 2) = __halves2bfloat162(h[2], h[3]);
    *(__nv_bfloat162*)(g_bufl + base)     = __halves2bfloat162(l[0], l[1]);
    *(__nv_bfloat162*)(g_bufl + base + 2) = __halves2bfloat162(l[2], l[3]);
}

// ---------------- weight split fp32 -> bf16 hi/lo ----------------
__global__ void conv_split_kernel(const float* __restrict__ src,
                                  __nv_bfloat16* __restrict__ dh,
                                  __nv_bfloat16* __restrict__ dl, int n4) {
    int i = blockIdx.x * 256 + threadIdx.x;
    if (i >= n4) return;
    float4 v = ((const float4*)src)[i];
    float vv[4] = {v.x, v.y, v.z, v.w};
    __nv_bfloat16 h[4], l[4];
#pragma unroll
    for (int k = 0; k < 4; k++) {
        h[k] = __float2bfloat16(vv[k]);
        l[k] = __float2bfloat16(vv[k] - __bfloat162float(h[k]));
    }
    size_t base = (size_t)i * 4;
    *(__nv_bfloat162*)(dh + base)     = __halves2bfloat162(h[0], h[1]);
    *(__nv_bfloat162*)(dh + base + 2) = __halves2bfloat162(h[2], h[3]);
    *(__nv_bfloat162*)(dl + base)     = __halves2bfloat162(l[0], l[1]);
    *(__nv_bfloat162*)(dl + base + 2) = __halves2bfloat162(l[2], l[3]);
}

// ---------------- mma.sync grouped GEMM, bf16 hi/lo 3-pass ----------------
// C[m,n] = sum_k A[m,k]*B[n,k]. BM=128, BN=128, BK=32, 4 stages cp.async.
// MODE 0: epilogue gelu(v + b1) -> g_hh/g_hl (bf16 hi/lo)
// MODE 1: epilogue v + b2 + residual -> g_eo (fp32)
#define STG_BYTES 32768      // 4 tiles of 128x32 bf16 (8KB each): Ah,Al,Bh,Bl
#define GEMM_SMEM (4 * STG_BYTES + 512)

template<int KDIM, int NTOT, int MODE>
__global__ void __launch_bounds__(256, 1)
moe_gemm(const __nv_bfloat16* __restrict__ Ah_g, const __nv_bfloat16* __restrict__ Al_g,
         const __nv_bfloat16* __restrict__ Bh_g, const __nv_bfloat16* __restrict__ Bl_g,
         const float* __restrict__ bias_g) {
    extern __shared__ char smem[];
    const int e = blockIdx.z;
    const int m0 = blockIdx.y * 128;
    if (m0 >= g_cnt[e]) return;
    const int n0 = blockIdx.x * 128;

    const int tid = threadIdx.x;
    const int lane = tid & 31;
    const int warp = tid >> 5;
    const int wm = warp & 3;          // 4 warps along M (32 rows each)
    const int wn = warp >> 2;         // 2 warps along N (64 cols each)
    const uint32_t sbase = smem_u32(smem);

    // bias tile -> smem
    float* sbias = (float*)(smem + 4 * STG_BYTES);
    for (int i = tid; i < 128; i += 256) sbias[i] = bias_g[(size_t)e * NTOT + n0 + i];

    const __nv_bfloat16* Ah = Ah_g + (size_t)(e * CAP + m0) * KDIM;
    const __nv_bfloat16* Al = Al_g + (size_t)(e * CAP + m0) * KDIM;
    const __nv_bfloat16* Bh = Bh_g + (size_t)(e * NTOT + n0) * KDIM;
    const __nv_bfloat16* Bl = Bl_g + (size_t)(e * NTOT + n0) * KDIM;

    // ldmatrix per-thread address precompute.
    // smem tile layout: row r (0..127) x 32 bf16 (64B), swizzled:
    //   off(r, cb) = r*64 + (cb ^ (((r>>1)&3)<<4)),  cb in {0,16,32,48}
    const int g8 = lane >> 3, lr = lane & 7;
    int aoff[2], asw[2];
#pragma unroll
    for (int mi = 0; mi < 2; mi++) {
        int r = wm * 32 + mi * 16 + (g8 & 1) * 8 + lr;
        aoff[mi] = r * 64;
        asw[mi] = ((r >> 1) & 3) << 4;
    }
    const int cbpa = (g8 >> 1) * 16;
    int boff[4], bsw[4];
#pragma unroll
    for (int p = 0; p < 4; p++) {
        int r = wn * 64 + p * 16 + (g8 >> 1) * 8 + lr;
        boff[p] = r * 64;
        bsw[p] = ((r >> 1) & 3) << 4;
    }
    const int cbpb = (g8 & 1) * 16;

    float acc[2][8][4];
#pragma unroll
    for (int mi = 0; mi < 2; mi++)
#pragma unroll
        for (int ni = 0; ni < 8; ni++)
#pragma unroll
            for (int q = 0; q < 4; q++) acc[mi][ni][q] = 0.f;

    // stage loader: 2048 16B chunks, 8 per thread; i<2:Ah, <4:Al, <6:Bh, else Bl
#define LOAD_STAGE(st, kt) do {                                                   \
        const int _k0 = (kt) * 32;                                                \
        const uint32_t _sb = sbase + (st) * STG_BYTES;                            \
        _Pragma("unroll")                                                         \
        for (int _i = 0; _i < 8; _i++) {                                          \
            const int _c = tid + _i * 256;                                        \
            const int _idx = _c & 511;                                            \
            const int _r = _idx >> 2;                                             \
            const int _cb = (_idx & 3) << 4;                                      \
            const uint32_t _sa = _sb + (_c >> 9) * 8192 + _r * 64 +               \
                                 (_cb ^ (((_r >> 1) & 3) << 4));                  \
            const __nv_bfloat16* _gp = (_i < 2) ? Ah : (_i < 4) ? Al              \
                                      : (_i < 6) ? Bh : Bl;                       \
            const __nv_bfloat16* _src = _gp + (size_t)_r * KDIM + _k0 + (_cb >> 1); \
            CP_ASYNC16(_sa, _src);                                                \
        }                                                                         \
    } while (0)

    constexpr int KT = KDIM / 32;
    LOAD_STAGE(0, 0); CP_COMMIT();
    LOAD_STAGE(1, 1); CP_COMMIT();
    LOAD_STAGE(2, 2); CP_COMMIT();

    for (int kt = 0; kt < KT; kt++) {
        CP_WAIT2();
        __syncthreads();
        if (kt + 3 < KT) { LOAD_STAGE((kt + 3) & 3, kt + 3); }
        CP_COMMIT();

        const uint32_t sA = sbase + (kt & 3) * STG_BYTES;
        const uint32_t sB = sA + 16384;
#pragma unroll
        for (int ks = 0; ks < 2; ks++) {
            uint32_t ah[2][4], al2[2][4], bh[4][4], bl[4][4];
#pragma unroll
            for (int mi = 0; mi < 2; mi++) {
                const uint32_t ad = sA + aoff[mi] + ((ks * 32 + cbpa) ^ asw[mi]);
                LDSM4(ah[mi], ad);
                LDSM4(al2[mi], ad + 8192);
            }
#pragma unroll
            for (int p = 0; p < 4; p++) {
                const uint32_t bd = sB + boff[p] + ((ks * 32 + cbpb) ^ bsw[p]);
                LDSM4(bh[p], bd);
                LDSM4(bl[p], bd + 8192);
            }
#pragma unroll
            for (int mi = 0; mi < 2; mi++)
#pragma unroll
                for (int ni = 0; ni < 8; ni++) {
                    uint32_t* bhp = &bh[ni >> 1][(ni & 1) * 2];
                    uint32_t* blp = &bl[ni >> 1][(ni & 1) * 2];
                    MMA_BF16(acc[mi][ni], ah[mi], bhp);     // hi*hi
                    MMA_BF16(acc[mi][ni], ah[mi], blp);     // hi*lo
                    MMA_BF16(acc[mi][ni], al2[mi], bhp);    // lo*hi
                }
        }
    }
#undef LOAD_STAGE

    // epilogue
#pragma unroll
    for (int mi = 0; mi < 2; mi++) {
        const int row0 = m0 + wm * 32 + mi * 16 + (lane >> 2);
#pragma unroll
        for (int half = 0; half < 2; half++) {
            const int row = row0 + half * 8;
            const size_t rowg = (size_t)(e * CAP) + row;
#pragma unroll
            for (int ni = 0; ni < 8; ni++) {
                const int cl = wn * 64 + ni * 8 + (lane & 3) * 2;
                const int col = n0 + cl;
                float v0 = acc[mi][ni][half * 2 + 0] + sbias[cl];
                float v1 = acc[mi][ni][half * 2 + 1] + sbias[cl + 1];
                if (MODE == 0) {
                    v0 = gelu_f(v0); v1 = gelu_f(v1);
                    __nv_bfloat16 h0 = __float2bfloat16(v0);
                    __nv_bfloat16 l0 = __float2bfloat16(v0 - __bfloat162float(h0));
                    __nv_bfloat16 h1 = __float2bfloat16(v1);
                    __nv_bfloat16 l1 = __float2bfloat16(v1 - __bfloat162float(h1));
                    const size_t idx = rowg * (size_t)F_DIM + col;
                    *(__nv_bfloat162*)(g_hh + idx) = __halves2bfloat162(h0, h1);
                    *(__nv_bfloat162*)(g_hl + idx) = __halves2bfloat162(l0, l1);
                } else {
                    const size_t idx = rowg * (size_t)D_DIM + col;
                    const __nv_bfloat162 rh = *(const __nv_bfloat162*)(g_bufh + idx);
                    const __nv_bfloat162 rl = *(const __nv_bfloat162*)(g_bufl + idx);
                    float2 o;
                    o.x = v0 + __bfloat162float(rh.x) + __bfloat162float(rl.x);
                    o.y = v1 + __bfloat162float(rh.y) + __bfloat162float(rl.y);
                    *(float2*)(g_eo + idx) = o;
                }
            }
        }
    }
}

// ---------------- combine ----------------
__global__ void combine_kernel(float* __restrict__ y) {
    const int s = blockIdx.x;
    const int a0 = 2 * s, a1 = 2 * s + 1;
    const int p0 = g_pos[a0], p1 = g_pos[a1];
    const float w0 = (p0 < CAP) ? g_gate[a0] : 0.f;
    const float w1 = (p1 < CAP) ? g_gate[a1] : 0.f;
    const int q0 = p0 < CAP ? p0 : CAP - 1;
    const int q1 = p1 < CAP ? p1 : CAP - 1;
    const float4* r0 = (const float4*)(g_eo + ((size_t)g_eidx[a0] * CAP + q0) * D_DIM);
    const float4* r1 = (const float4*)(g_eo + ((size_t)g_eidx[a1] * CAP + q1) * D_DIM);
    float4* yo = (float4*)(y + (size_t)s * D_DIM);
    const int i = threadIdx.x;
    const float4 v0 = r0[i];
    const float4 v1 = r1[i];
    float4 o;
    o.x = w0 * v0.x + w1 * v1.x;
    o.y = w0 * v0.y + w1 * v1.y;
    o.z = w0 * v0.z + w1 * v1.z;
    o.w = w0 * v0.w + w1 * v1.w;
    yo[i] = o;
}

// ---------------- aux loss ----------------
__global__ void importance_kernel() {
    __shared__ float sm[256];
    const int e = blockIdx.x;
    float a = 0.f;
    for (int s = threadIdx.x; s < S_TOK; s += 256) a += g_probs[s * E_NUM + e];
    sm[threadIdx.x] = a;
    __syncthreads();
    for (int o = 128; o > 0; o >>= 1) {
        if (threadIdx.x < o) sm[threadIdx.x] += sm[threadIdx.x + o];
        __syncthreads();
    }
    if (threadIdx.x == 0) g_importance[e] = sm[0];
}
__global__ void aux_kernel(float* __restrict__ out, int out_size) {
    if (threadIdx.x == 0) {
        float a = 0.f;
#pragma unroll
        for (int e = 0; e < E_NUM; e++)
            a += (g_importance[e] / (float)S_TOK) * ((float)g_counts[e] / (float)S_TOK);
        out[out_size - 1] = (float)E_NUM * a;
    }
}

// ---------------- host ----------------
extern "C" void kernel_launch(void* const* d_in, const int* in_sizes, int n_in,
                              void* d_out, int out_size) {
    const float* x  = (const float*)d_in[0];
    const float* wg = (const float*)d_in[1];
    const float* W1 = (const float*)d_in[2];
    const float* b1 = (const float*)d_in[3];
    const float* W2 = (const float*)d_in[4];
    const float* b2 = (const float*)d_in[5];
    float* out = (float*)d_out;

    void *bufh, *bufl, *hh, *hl, *w1h, *w1l, *w2h, *w2l;
    cudaGetSymbolAddress(&bufh, g_bufh); cudaGetSymbolAddress(&bufl, g_bufl);
    cudaGetSymbolAddress(&hh, g_hh);     cudaGetSymbolAddress(&hl, g_hl);
    cudaGetSymbolAddress(&w1h, g_w1h);   cudaGetSymbolAddress(&w1l, g_w1l);
    cudaGetSymbolAddress(&w2h, g_w2h);   cudaGetSymbolAddress(&w2l, g_w2l);

    cudaFuncSetAttribute(moe_gemm<D_DIM, F_DIM, 0>,
                         cudaFuncAttributeMaxDynamicSharedMemorySize, GEMM_SMEM);
    cudaFuncSetAttribute(moe_gemm<F_DIM, D_DIM, 1>,
                         cudaFuncAttributeMaxDynamicSharedMemorySize, GEMM_SMEM);

    routing_kernel<<<S_TOK, 256>>>(x, wg);
    scan_kernel<<<1, 256>>>();
    dispatch_kernel<<<A_NUM, 256>>>(x);
    const int w1n4 = E_NUM * F_DIM * D_DIM / 4;
    conv_split_kernel<<<(w1n4 + 255) / 256, 256>>>(W1, (__nv_bfloat16*)w1h, (__nv_bfloat16*)w1l, w1n4);
    const int w2n4 = E_NUM * D_DIM * F_DIM / 4;
    conv_split_kernel<<<(w2n4 + 255) / 256, 256>>>(W2, (__nv_bfloat16*)w2h, (__nv_bfloat16*)w2l, w2n4);

    moe_gemm<D_DIM, F_DIM, 0><<<dim3(F_DIM / 128, CAP / 128, E_NUM), 256, GEMM_SMEM>>>(
        (const __nv_bfloat16*)bufh, (const __nv_bfloat16*)bufl,
        (const __nv_bfloat16*)w1h, (const __nv_bfloat16*)w1l, b1);
    moe_gemm<F_DIM, D_DIM, 1><<<dim3(D_DIM / 128, CAP / 128, E_NUM), 256, GEMM_SMEM>>>(
        (const __nv_bfloat16*)hh, (const __nv_bfloat16*)hl,
        (const __nv_bfloat16*)w2h, (const __nv_bfloat16*)w2l, b2);

    combine_kernel<<<S_TOK, 256>>>(out);
    importance_kernel<<<E_NUM, 256>>>();
    aux_kernel<<<1, 32>>>(out, out_size);
}

// round 16
// speedup vs baseline: 3.8910x; 1.3500x over previous
#include <cuda_runtime.h>
#include <cuda_fp16.h>
#include <math.h>
#include <stdint.h>

// ---------------- problem constants ----------------
#define S_TOK 8192
#define D_DIM 1024
#define F_DIM 4096
#define E_NUM 8
#define CAP   2560
#define A_NUM (S_TOK * 2)

// ---------------- device scratch ----------------
__device__ float g_probs[S_TOK * E_NUM];
__device__ int   g_eidx[A_NUM];
__device__ float g_gate[A_NUM];
__device__ int   g_pos[A_NUM];
__device__ int   g_counts[E_NUM];
__device__ int   g_cnt[E_NUM];
__device__ float g_importance[E_NUM];

__device__ __align__(1024) __half g_bufh[(size_t)E_NUM * CAP * D_DIM];
__device__ __align__(1024) __half g_bufl[(size_t)E_NUM * CAP * D_DIM];
__device__ __align__(1024) __half g_hh[(size_t)E_NUM * CAP * F_DIM];
__device__ __align__(1024) __half g_hl[(size_t)E_NUM * CAP * F_DIM];
__device__ __align__(1024) __half g_w1h[(size_t)E_NUM * F_DIM * D_DIM];
__device__ __align__(1024) __half g_w2h[(size_t)E_NUM * D_DIM * F_DIM];
__device__ __align__(1024) float g_eo[(size_t)E_NUM * CAP * D_DIM];

// ---------------- helpers ----------------
__device__ __forceinline__ uint32_t smem_u32(const void* p) {
    uint32_t a;
    asm("{ .reg .u64 t; cvta.to.shared.u64 t, %1; cvt.u32.u64 %0, t; }" : "=r"(a) : "l"(p));
    return a;
}
__device__ __forceinline__ float gelu_f(float v) {
    return 0.5f * v * (1.0f + erff(v * 0.70710678118654752f));
}

#define CP_ASYNC16(sa, ga) \
    asm volatile("cp.async.cg.shared.global [%0], [%1], 16;" :: "r"(sa), "l"(ga) : "memory")
#define CP_COMMIT() asm volatile("cp.async.commit_group;" ::: "memory")
#define CP_WAIT2()  asm volatile("cp.async.wait_group 2;" ::: "memory")

#define LDSM4(R, addr) \
    asm volatile("ldmatrix.sync.aligned.m8n8.x4.shared.b16 {%0,%1,%2,%3}, [%4];" \
        : "=r"((R)[0]), "=r"((R)[1]), "=r"((R)[2]), "=r"((R)[3]) : "r"(addr))

#define MMA_F16(D, A, B) \
    asm volatile("mma.sync.aligned.m16n8k16.row.col.f32.f16.f16.f32 " \
        "{%0,%1,%2,%3}, {%4,%5,%6,%7}, {%8,%9}, {%0,%1,%2,%3};" \
        : "+f"((D)[0]), "+f"((D)[1]), "+f"((D)[2]), "+f"((D)[3]) \
        : "r"((A)[0]), "r"((A)[1]), "r"((A)[2]), "r"((A)[3]), "r"((B)[0]), "r"((B)[1]))

// ---------------- routing ----------------
__global__ void routing_kernel(const float* __restrict__ x, const float* __restrict__ wg) {
    __shared__ float swg[E_NUM * D_DIM];
    const int s = blockIdx.x;
    const int tid = threadIdx.x;
    for (int i = tid; i < E_NUM * D_DIM; i += 256) swg[i] = wg[i];
    __syncthreads();
    const float* xr = x + (size_t)s * D_DIM;
    float p[E_NUM];
#pragma unroll
    for (int e = 0; e < E_NUM; e++) p[e] = 0.f;
    for (int d = tid; d < D_DIM; d += 256) {
        float xv = xr[d];
#pragma unroll
        for (int e = 0; e < E_NUM; e++) p[e] = fmaf(xv, swg[e * D_DIM + d], p[e]);
    }
#pragma unroll
    for (int e = 0; e < E_NUM; e++)
        for (int o = 16; o > 0; o >>= 1) p[e] += __shfl_down_sync(0xffffffffu, p[e], o);
    __shared__ float wsum[8][E_NUM];
    const int wid = tid >> 5, lane = tid & 31;
    if (lane == 0) {
#pragma unroll
        for (int e = 0; e < E_NUM; e++) wsum[wid][e] = p[e];
    }
    __syncthreads();
    if (tid == 0) {
        float l[E_NUM];
#pragma unroll
        for (int e = 0; e < E_NUM; e++) {
            float a = 0.f;
#pragma unroll
            for (int w = 0; w < 8; w++) a += wsum[w][e];
            l[e] = a;
        }
        float mx = l[0];
#pragma unroll
        for (int e = 1; e < E_NUM; e++) mx = fmaxf(mx, l[e]);
        float pr[E_NUM], se = 0.f;
#pragma unroll
        for (int e = 0; e < E_NUM; e++) { pr[e] = expf(l[e] - mx); se += pr[e]; }
        const float inv = 1.f / se;
#pragma unroll
        for (int e = 0; e < E_NUM; e++) { pr[e] *= inv; g_probs[s * E_NUM + e] = pr[e]; }
        int b0 = 0;
#pragma unroll
        for (int e = 1; e < E_NUM; e++) if (l[e] > l[b0]) b0 = e;
        int b1 = -1;
#pragma unroll
        for (int e = 0; e < E_NUM; e++) {
            if (e == b0) continue;
            if (b1 < 0 || l[e] > l[b1]) b1 = e;
        }
        g_eidx[s * 2 + 0] = b0;  g_gate[s * 2 + 0] = pr[b0];
        g_eidx[s * 2 + 1] = b1;  g_gate[s * 2 + 1] = pr[b1];
    }
}

// ---------------- capacity scan ----------------
__global__ void scan_kernel() {
    __shared__ int hist[256][E_NUM];
    const int t = threadIdx.x;
    const int base = t * 64;
    int loc[E_NUM];
#pragma unroll
    for (int e = 0; e < E_NUM; e++) loc[e] = 0;
    for (int i = 0; i < 64; i++) loc[g_eidx[base + i]]++;
#pragma unroll
    for (int e = 0; e < E_NUM; e++) hist[t][e] = loc[e];
    __syncthreads();
    if (t < E_NUM) {
        int run = 0;
        for (int i = 0; i < 256; i++) { int v = hist[i][t]; hist[i][t] = run; run += v; }
        g_counts[t] = run;
        g_cnt[t] = run < CAP ? run : CAP;
    }
    __syncthreads();
    int off[E_NUM];
#pragma unroll
    for (int e = 0; e < E_NUM; e++) off[e] = hist[t][e];
    for (int i = 0; i < 64; i++) {
        int e = g_eidx[base + i];
        g_pos[base + i] = off[e]++;
    }
}

// ---------------- dispatch: tokens -> fp16 hi/lo buffers ----------------
__global__ void dispatch_kernel(const float* __restrict__ x) {
    const int a = blockIdx.x;
    const int p = g_pos[a];
    if (p >= CAP) return;
    const int e = g_eidx[a];
    const int t = a >> 1;
    const float4 v = ((const float4*)(x + (size_t)t * D_DIM))[threadIdx.x];
    const size_t base = ((size_t)e * CAP + p) * D_DIM + threadIdx.x * 4;
    float vv[4] = {v.x, v.y, v.z, v.w};
    __half h[4], l[4];
#pragma unroll
    for (int i = 0; i < 4; i++) {
        h[i] = __float2half(vv[i]);
        l[i] = __float2half(vv[i] - __half2float(h[i]));
    }
    *(__half2*)(g_bufh + base)     = __halves2half2(h[0], h[1]);
    *(__half2*)(g_bufh + base + 2) = __halves2half2(h[2], h[3]);
    *(__half2*)(g_bufl + base)     = __halves2half2(l[0], l[1]);
    *(__half2*)(g_bufl + base + 2) = __halves2half2(l[2], l[3]);
}

// ---------------- weight convert fp32 -> fp16 (hi only) ----------------
__global__ void conv_half_kernel(const float* __restrict__ src,
                                 __half* __restrict__ dh, int n4) {
    int i = blockIdx.x * 256 + threadIdx.x;
    if (i >= n4) return;
    float4 v = ((const float4*)src)[i];
    __half2 a = __halves2half2(__float2half(v.x), __float2half(v.y));
    __half2 b = __halves2half2(__float2half(v.z), __float2half(v.w));
    size_t base = (size_t)i * 4;
    *(__half2*)(dh + base)     = a;
    *(__half2*)(dh + base + 2) = b;
}

// ---------------- mma.sync grouped GEMM, fp16 2-pass (Ah*Bh + Al*Bh) ----------------
// C[m,n] = sum_k A[m,k]*B[n,k]. BM=128, BN=128, BK=32, 4 stages cp.async.
// MODE 0: epilogue gelu(v + b1) -> g_hh/g_hl (fp16 hi/lo)
// MODE 1: epilogue v + b2 + residual -> g_eo (fp32)
#define STG_BYTES 24576      // 3 tiles of 128x32 fp16 (8KB each): Ah, Al, Bh
#define GEMM_SMEM (4 * STG_BYTES + 512)

template<int KDIM, int NTOT, int MODE>
__global__ void __launch_bounds__(256, 1)
moe_gemm(const __half* __restrict__ Ah_g, const __half* __restrict__ Al_g,
         const __half* __restrict__ Bh_g,
         const float* __restrict__ bias_g) {
    extern __shared__ char smem[];
    const int e = blockIdx.z;
    const int m0 = blockIdx.y * 128;
    if (m0 >= g_cnt[e]) return;
    const int n0 = blockIdx.x * 128;

    const int tid = threadIdx.x;
    const int lane = tid & 31;
    const int warp = tid >> 5;
    const int wm = warp & 3;          // 4 warps along M (32 rows each)
    const int wn = warp >> 2;         // 2 warps along N (64 cols each)
    const uint32_t sbase = smem_u32(smem);

    // bias tile -> smem
    float* sbias = (float*)(smem + 4 * STG_BYTES);
    for (int i = tid; i < 128; i += 256) sbias[i] = bias_g[(size_t)e * NTOT + n0 + i];

    const __half* Ah = Ah_g + (size_t)(e * CAP + m0) * KDIM;
    const __half* Al = Al_g + (size_t)(e * CAP + m0) * KDIM;
    const __half* Bh = Bh_g + (size_t)(e * NTOT + n0) * KDIM;

    // ldmatrix per-thread address precompute.
    // smem tile layout: row r (0..127) x 32 fp16 (64B), swizzled:
    //   off(r, cb) = r*64 + (cb ^ (((r>>1)&3)<<4)),  cb in {0,16,32,48}
    const int g8 = lane >> 3, lr = lane & 7;
    int aoff[2], asw[2];
#pragma unroll
    for (int mi = 0; mi < 2; mi++) {
        int r = wm * 32 + mi * 16 + (g8 & 1) * 8 + lr;
        aoff[mi] = r * 64;
        asw[mi] = ((r >> 1) & 3) << 4;
    }
    const int cbpa = (g8 >> 1) * 16;
    int boff[4], bsw[4];
#pragma unroll
    for (int p = 0; p < 4; p++) {
        int r = wn * 64 + p * 16 + (g8 >> 1) * 8 + lr;
        boff[p] = r * 64;
        bsw[p] = ((r >> 1) & 3) << 4;
    }
    const int cbpb = (g8 & 1) * 16;

    float acc[2][8][4];
#pragma unroll
    for (int mi = 0; mi < 2; mi++)
#pragma unroll
        for (int ni = 0; ni < 8; ni++)
#pragma unroll
            for (int q = 0; q < 4; q++) acc[mi][ni][q] = 0.f;

    // stage loader: 1536 16B chunks, 6 per thread; i<2:Ah, <4:Al, else Bh
#define LOAD_STAGE(st, kt) do {                                                   \
        const int _k0 = (kt) * 32;                                                \
        const uint32_t _sb = sbase + (st) * STG_BYTES;                            \
        _Pragma("unroll")                                                         \
        for (int _i = 0; _i < 6; _i++) {                                          \
            const int _c = tid + _i * 256;                                        \
            const int _idx = _c & 511;                                            \
            const int _r = _idx >> 2;                                             \
            const int _cb = (_idx & 3) << 4;                                      \
            const uint32_t _sa = _sb + (_c >> 9) * 8192 + _r * 64 +               \
                                 (_cb ^ (((_r >> 1) & 3) << 4));                  \
            const __half* _gp = (_i < 2) ? Ah : (_i < 4) ? Al : Bh;               \
            const __half* _src = _gp + (size_t)_r * KDIM + _k0 + (_cb >> 1);      \
            CP_ASYNC16(_sa, _src);                                                \
        }                                                                         \
    } while (0)

    constexpr int KT = KDIM / 32;
    LOAD_STAGE(0, 0); CP_COMMIT();
    LOAD_STAGE(1, 1); CP_COMMIT();
    LOAD_STAGE(2, 2); CP_COMMIT();

    for (int kt = 0; kt < KT; kt++) {
        CP_WAIT2();
        __syncthreads();
        if (kt + 3 < KT) { LOAD_STAGE((kt + 3) & 3, kt + 3); }
        CP_COMMIT();

        const uint32_t sA = sbase + (kt & 3) * STG_BYTES;
        const uint32_t sB = sA + 16384;
#pragma unroll
        for (int ks = 0; ks < 2; ks++) {
            uint32_t ah[2][4], al2[2][4], bh[4][4];
#pragma unroll
            for (int mi = 0; mi < 2; mi++) {
                const uint32_t ad = sA + aoff[mi] + ((ks * 32 + cbpa) ^ asw[mi]);
                LDSM4(ah[mi], ad);
                LDSM4(al2[mi], ad + 8192);
            }
#pragma unroll
            for (int p = 0; p < 4; p++) {
                const uint32_t bd = sB + boff[p] + ((ks * 32 + cbpb) ^ bsw[p]);
                LDSM4(bh[p], bd);
            }
#pragma unroll
            for (int mi = 0; mi < 2; mi++)
#pragma unroll
                for (int ni = 0; ni < 8; ni++) {
                    uint32_t* bhp = &bh[ni >> 1][(ni & 1) * 2];
                    MMA_F16(acc[mi][ni], ah[mi], bhp);     // hi*hi
                    MMA_F16(acc[mi][ni], al2[mi], bhp);    // lo*hi
                }
        }
    }
#undef LOAD_STAGE

    // epilogue
#pragma unroll
    for (int mi = 0; mi < 2; mi++) {
        const int row0 = m0 + wm * 32 + mi * 16 + (lane >> 2);
#pragma unroll
        for (int half = 0; half < 2; half++) {
            const int row = row0 + half * 8;
            const size_t rowg = (size_t)(e * CAP) + row;
#pragma unroll
            for (int ni = 0; ni < 8; ni++) {
                const int cl = wn * 64 + ni * 8 + (lane & 3) * 2;
                const int col = n0 + cl;
                float v0 = acc[mi][ni][half * 2 + 0] + sbias[cl];
                float v1 = acc[mi][ni][half * 2 + 1] + sbias[cl + 1];
                if (MODE == 0) {
                    v0 = gelu_f(v0); v1 = gelu_f(v1);
                    __half h0 = __float2half(v0);
                    __half l0 = __float2half(v0 - __half2float(h0));
                    __half h1 = __float2half(v1);
                    __half l1 = __float2half(v1 - __half2float(h1));
                    const size_t idx = rowg * (size_t)F_DIM + col;
                    *(__half2*)(g_hh + idx) = __halves2half2(h0, h1);
                    *(__half2*)(g_hl + idx) = __halves2half2(l0, l1);
                } else {
                    const size_t idx = rowg * (size_t)D_DIM + col;
                    const __half2 rh = *(const __half2*)(g_bufh + idx);
                    const __half2 rl = *(const __half2*)(g_bufl + idx);
                    float2 o;
                    o.x = v0 + __half2float(__low2half(rh)) + __half2float(__low2half(rl));
                    o.y = v1 + __half2float(__high2half(rh)) + __half2float(__high2half(rl));
                    *(float2*)(g_eo + idx) = o;
                }
            }
        }
    }
}

// ---------------- combine ----------------
__global__ void combine_kernel(float* __restrict__ y) {
    const int s = blockIdx.x;
    const int a0 = 2 * s, a1 = 2 * s + 1;
    const int p0 = g_pos[a0], p1 = g_pos[a1];
    const float w0 = (p0 < CAP) ? g_gate[a0] : 0.f;
    const float w1 = (p1 < CAP) ? g_gate[a1] : 0.f;
    const int q0 = p0 < CAP ? p0 : CAP - 1;
    const int q1 = p1 < CAP ? p1 : CAP - 1;
    const float4* r0 = (const float4*)(g_eo + ((size_t)g_eidx[a0] * CAP + q0) * D_DIM);
    const float4* r1 = (const float4*)(g_eo + ((size_t)g_eidx[a1] * CAP + q1) * D_DIM);
    float4* yo = (float4*)(y + (size_t)s * D_DIM);
    const int i = threadIdx.x;
    const float4 v0 = r0[i];
    const float4 v1 = r1[i];
    float4 o;
    o.x = w0 * v0.x + w1 * v1.x;
    o.y = w0 * v0.y + w1 * v1.y;
    o.z = w0 * v0.z + w1 * v1.z;
    o.w = w0 * v0.w + w1 * v1.w;
    yo[i] = o;
}

// ---------------- aux loss ----------------
__global__ void importance_kernel() {
    __shared__ float sm[256];
    const int e = blockIdx.x;
    float a = 0.f;
    for (int s = threadIdx.x; s < S_TOK; s += 256) a += g_probs[s * E_NUM + e];
    sm[threadIdx.x] = a;
    __syncthreads();
    for (int o = 128; o > 0; o >>= 1) {
        if (threadIdx.x < o) sm[threadIdx.x] += sm[threadIdx.x + o];
        __syncthreads();
    }
    if (threadIdx.x == 0) g_importance[e] = sm[0];
}
__global__ void aux_kernel(float* __restrict__ out, int out_size) {
    if (threadIdx.x == 0) {
        float a = 0.f;
#pragma unroll
        for (int e = 0; e < E_NUM; e++)
            a += (g_importance[e] / (float)S_TOK) * ((float)g_counts[e] / (float)S_TOK);
        out[out_size - 1] = (float)E_NUM * a;
    }
}

// ---------------- host ----------------
extern "C" void kernel_launch(void* const* d_in, const int* in_sizes, int n_in,
                              void* d_out, int out_size) {
    const float* x  = (const float*)d_in[0];
    const float* wg = (const float*)d_in[1];
    const float* W1 = (const float*)d_in[2];
    const float* b1 = (const float*)d_in[3];
    const float* W2 = (const float*)d_in[4];
    const float* b2 = (const float*)d_in[5];
    float* out = (float*)d_out;

    void *bufh, *bufl, *hh, *hl, *w1h, *w2h;
    cudaGetSymbolAddress(&bufh, g_bufh); cudaGetSymbolAddress(&bufl, g_bufl);
    cudaGetSymbolAddress(&hh, g_hh);     cudaGetSymbolAddress(&hl, g_hl);
    cudaGetSymbolAddress(&w1h, g_w1h);   cudaGetSymbolAddress(&w2h, g_w2h);

    cudaFuncSetAttribute(moe_gemm<D_DIM, F_DIM, 0>,
                         cudaFuncAttributeMaxDynamicSharedMemorySize, GEMM_SMEM);
    cudaFuncSetAttribute(moe_gemm<F_DIM, D_DIM, 1>,
                         cudaFuncAttributeMaxDynamicSharedMemorySize, GEMM_SMEM);

    routing_kernel<<<S_TOK, 256>>>(x, wg);
    scan_kernel<<<1, 256>>>();
    dispatch_kernel<<<A_NUM, 256>>>(x);
    const int w1n4 = E_NUM * F_DIM * D_DIM / 4;
    conv_half_kernel<<<(w1n4 + 255) / 256, 256>>>(W1, (__half*)w1h, w1n4);
    const int w2n4 = E_NUM * D_DIM * F_DIM / 4;
    conv_half_kernel<<<(w2n4 + 255) / 256, 256>>>(W2, (__half*)w2h, w2n4);

    moe_gemm<D_DIM, F_DIM, 0><<<dim3(F_DIM / 128, CAP / 128, E_NUM), 256, GEMM_SMEM>>>(
        (const __half*)bufh, (const __half*)bufl, (const __half*)w1h, b1);
    moe_gemm<F_DIM, D_DIM, 1><<<dim3(D_DIM / 128, CAP / 128, E_NUM), 256, GEMM_SMEM>>>(
        (const __half*)hh, (const __half*)hl, (const __half*)w2h, b2);

    combine_kernel<<<S_TOK, 256>>>(out);
    importance_kernel<<<E_NUM, 256>>>();
    aux_kernel<<<1, 32>>>(out, out_size);
}